// round 15
// baseline (speedup 1.0000x reference)
#include <cuda_runtime.h>

// ---------------- problem constants ----------------
#define BATCH   256
#define NSAMP   16000
#define CCH     32
#define KTAP    64
#define NCHUNK  125          // 128-sample chunks covering 16000 samples
#define TSTEPS  124
#define HID     50
#define HIDP    52           // padded row stride
#define OUT     10
#define ANS     10

#define GROUP   8            // chunks per conv block (one per warp)
#define SEG     (GROUP*128)  // 1024 positions per block
#define SWIN    1088         // staged window length per shifted copy
#define SPITCH  1104         // padded copy pitch (floats)
#define NGRPX   16           // conv position groups

// scan kernel dynamic smem layout (floats)
#define BUF1_N  (TSTEPS * HIDP)          // 6448 : bushy cur -> spk (in place)
#define BUF2_N  (TSTEPS * HIDP)          // 6448 : IC cur -> spk (in place)
#define BUFAC_N (TSTEPS * OUT * 2)       // 2480 : AC cur->spk | mem
#define WIC_N   (HID * HID)              // 2500
#define WAC_N   (OUT * HID)              // 500
#define SCAN_DYN_FLOATS (BUF1_N + BUF2_N + BUFAC_N + WIC_N + WAC_N)
#define SCAN_DYN_BYTES  (SCAN_DYN_FLOATS * 4)

// ---------------- device scratch (no allocs allowed) ----------------
__device__ float  S_buf[BATCH * NCHUNK * CCH];                       // per-chunk relu sums
__device__ __align__(16) float SufW_g[CCH * (ANS + 1) * HIDP];       // padded suffix sums

// ---------------- helpers ----------------
__device__ __forceinline__ unsigned s2u(const void* p) {
    return (unsigned)__cvta_generic_to_shared(p);
}
#define FFMA2(acc, a, b) \
    asm("fma.rn.f32x2 %0, %1, %2, %0;" : "+l"(acc) : "l"(a), "l"(b))
#define ADD2(acc, v) \
    asm("add.rn.f32x2 %0, %0, %1;" : "+l"(acc) : "l"(v))
#define LDSV2(lo, hi, addr) \
    asm("ld.shared.v2.b64 {%0, %1}, [%2];" : "=l"(lo), "=l"(hi) : "r"(addr))
#define LDG2U64(lo, hi, ptr) \
    asm("ld.global.nc.v2.u64 {%0, %1}, [%2];" : "=l"(lo), "=l"(hi) : "l"(ptr))

// ---------------- kernel B: fused gammatone conv + relu + chunk-sum ----------------
// grid (17, BATCH): blockIdx.x < 16 -> conv tile; blockIdx.x == 16, y == 0 -> prep.
__global__ void __launch_bounds__(256, 2) conv_pool_kernel(const float* __restrict__ audio,
                                                           const float* __restrict__ gt,
                                                           const float* __restrict__ Wb) {
    const int tid = threadIdx.x;

    if (blockIdx.x == NGRPX) {
        // ---- prep block: suffix sums of W_bushy (runs in conv's shadow) ----
        if (blockIdx.y != 0) return;
        for (int id = tid; id < 1792; id += 256) {
            if (id < CCH * (ANS + 1)) {           // zero pad columns
                SufW_g[id * HIDP + 50] = 0.0f;
                SufW_g[id * HIDP + 51] = 0.0f;
            }
            if (id < HID * CCH) {
                int h = id / CCH;
                int c = id % CCH;
                SufW_g[(c * 11 + 10) * HIDP + h] = 0.0f;
                float v[ANS];
                #pragma unroll
                for (int a = 0; a < ANS; a++)
                    v[a] = Wb[h * (CCH * ANS) + c * ANS + a];
                float s = 0.0f;
                #pragma unroll
                for (int a = ANS - 1; a >= 0; a--) {
                    s += v[a];
                    SufW_g[(c * 11 + a) * HIDP + h] = s;
                }
            }
        }
        return;
    }

    const int grp = blockIdx.x;
    const int b   = blockIdx.y;
    __shared__ __align__(16) float s_copy[4][SPITCH];  // 4 shifted copies of audio window
    __shared__ float s_gt[KTAP * 33];                  // swizzled taps [k*33+c]

    const int P0  = grp * SEG;
    const float* abase = audio + b * NSAMP;

    #pragma unroll
    for (int s = 0; s < 4; s++) {
        for (int i = tid; i < SWIN; i += 256) {
            int n = P0 - 31 + i + s;
            s_copy[s][i] = (n >= 0 && n < NSAMP) ? abase[n] : 0.0f;
        }
    }
    for (int t = tid; t < CCH * KTAP; t += 256) {
        int c = t >> 6, k = t & 63;
        s_gt[k * 33 + c] = gt[t];
    }
    __syncthreads();

    const int c = tid & 31;   // channel = lane
    const int g = tid >> 5;   // warp id = local chunk

    unsigned long long kp[32];
    #pragma unroll
    for (int j = 0; j < 32; j++) {
        float t0 = s_gt[(2 * j) * 33 + c];
        float t1 = s_gt[(2 * j + 1) * 33 + c];
        asm("mov.b64 %0, {%1, %2};" : "=l"(kp[j]) : "f"(t0), "f"(t1));
    }

    const unsigned sbase = s2u(&s_copy[0][0]);
    float chunkacc = 0.0f;

    #pragma unroll 1
    for (int pass = 0; pass < 16; pass++) {
        const int h  = pass >> 2;        // 0..3 : which 32-position quarter
        const int c4 = pass & 3;         // copy index = position mod 4
        const int base = g * 128 + 32 * h;
        const unsigned addr = sbase + (unsigned)((c4 * SPITCH + base) * 4);

        unsigned long long accL[8], accH[8];
        #pragma unroll
        for (int j = 0; j < 8; j++) { accL[j] = 0ull; accH[j] = 0ull; }

        #pragma unroll
        for (int u = 0; u < 23; u++) {
            unsigned long long lo, hi;
            LDSV2(lo, hi, addr + 16u * (unsigned)u);
            #pragma unroll
            for (int j = 0; j < 8; j++) {
                const int m = u - j;
                if (m >= 0 && m < 16) {
                    FFMA2(accL[j], lo, kp[2 * m]);
                    FFMA2(accH[j], hi, kp[2 * m + 1]);
                }
            }
        }

        #pragma unroll
        for (int j = 0; j < 8; j++) {
            float l0, l1, h0, h1;
            asm("mov.b64 {%0, %1}, %2;" : "=f"(l0), "=f"(l1) : "l"(accL[j]));
            asm("mov.b64 {%0, %1}, %2;" : "=f"(h0), "=f"(h1) : "l"(accH[j]));
            float y = (l0 + l1) + (h0 + h1);
            chunkacc += fmaxf(y, 0.0f);
        }
    }

    const int j = grp * GROUP + g;
    if (j < NCHUNK)
        S_buf[(b * NCHUNK + j) * CCH + c] = chunkacc;
}

// ---------------- kernel C: phase-split LIF scan, smem-staged weights ----------------
// 256 threads per block, one block per batch element.
__global__ void __launch_bounds__(256, 2) scan_kernel(const float* __restrict__ Wic,
                                                      const float* __restrict__ Wac,
                                                      float* __restrict__ out, int half) {
    const int b = blockIdx.x;
    extern __shared__ __align__(16) float dyn[];
    float* buf1  = dyn;                  // [124][52] bushy cur -> spk
    float* buf2  = buf1 + BUF1_N;        // [124][52] IC cur -> spk
    float* bufAC = buf2 + BUF2_N;        // [124][10] AC spk | [124][10] AC mem
    float* sWic  = bufAC + BUFAC_N;      // [50*50] staged coalesced
    float* sWac  = sWic + WIC_N;         // [10*50]
    __shared__ unsigned short sOff[TSTEPS * CCH];

    const int tid = threadIdx.x;
    const int w   = tid >> 5;
    const int l   = tid & 31;
    const float beta = 0.95f;

    // ---- P0a: stage weights coalesced into smem ----
    for (int i = tid; i < WIC_N; i += 256) sWic[i] = __ldg(Wic + i);
    for (int i = tid; i < WAC_N; i += 256) sWac[i] = __ldg(Wac + i);

    // ---- P0b: per-(t,c) suffix offsets ----
    for (int x = tid; x < TSTEPS * CCH; x += 256) {
        int t = x >> 5, c = x & 31;
        float s0 = S_buf[(b * NCHUNK + t) * CCH + c];
        float s1 = S_buf[(b * NCHUNK + t + 1) * CCH + c];
        float env = (s0 + s1) * (1.0f / 256.0f);
        int cnt = 0;
        #pragma unroll
        for (int a = 0; a < ANS; a++) {
            float sc = 0.5f + (float)a * (1.0f / 9.0f);
            cnt += (env * sc - 0.5f) > 0.0f;
        }
        sOff[x] = (unsigned short)((c * 11 + (ANS - cnt)) * HIDP);
    }
    __syncthreads();

    // ---- P1: gather bushy input currents (packed f32x2 adds, L1-resident SufW) ----
    for (int x = tid; x < TSTEPS * (HIDP / 4); x += 256) {
        int t = x / (HIDP / 4);
        int q = x - t * (HIDP / 4);
        const unsigned short* off = &sOff[t * CCH];
        unsigned long long e01 = 0ull, e23 = 0ull, o01 = 0ull, o23 = 0ull;
        #pragma unroll 8
        for (int c = 0; c < CCH; c += 2) {
            unsigned long long a0, a1, b0, b1;
            LDG2U64(a0, a1, SufW_g + off[c] + 4 * q);
            LDG2U64(b0, b1, SufW_g + off[c + 1] + 4 * q);
            ADD2(e01, a0); ADD2(e23, a1);
            ADD2(o01, b0); ADD2(o23, b1);
        }
        unsigned long long r01, r23;
        asm("add.rn.f32x2 %0, %1, %2;" : "=l"(r01) : "l"(e01), "l"(o01));
        asm("add.rn.f32x2 %0, %1, %2;" : "=l"(r23) : "l"(e23), "l"(o23));
        unsigned saddr = s2u(&buf1[t * HIDP + 4 * q]);
        asm volatile("st.shared.v2.b64 [%0], {%1, %2};" :: "r"(saddr), "l"(r01), "l"(r23));
    }
    __syncthreads();

    // ---- P2: bushy membrane scans (50 independent units) ----
    if (tid < HID) {
        float mem = 0.0f;
        #pragma unroll 4
        for (int t = 0; t < TSTEPS; t++) {
            float cur = buf1[t * HIDP + tid];
            mem = fmaf(beta, mem, cur);
            float spk = (mem > 1.0f) ? 1.0f : 0.0f;
            mem -= spk;
            buf1[t * HIDP + tid] = spk;    // in place: cur -> spk
        }
    }
    __syncthreads();

    // ---- P3: IC GEMM, register weights from smem, float4 spike loads ----
    {
        float2 wR[25];
        {
            const float* row = sWic + l * HID;
            #pragma unroll
            for (int j = 0; j < 25; j++)
                wR[j] = make_float2(row[2 * j], row[2 * j + 1]);
        }
        #pragma unroll 1
        for (int t = w; t < TSTEPS; t += 8) {
            const float4* sp4 = (const float4*)&buf1[t * HIDP];
            float a0 = 0.f, a1 = 0.f;
            #pragma unroll
            for (int j = 0; j < 12; j++) {
                float4 s = sp4[j];
                a0 = fmaf(s.x, wR[2 * j].x, a0);
                a1 = fmaf(s.y, wR[2 * j].y, a1);
                a0 = fmaf(s.z, wR[2 * j + 1].x, a0);
                a1 = fmaf(s.w, wR[2 * j + 1].y, a1);
            }
            {
                float2 s24 = *(const float2*)&buf1[t * HIDP + 48];
                a0 = fmaf(s24.x, wR[24].x, a0);
                a1 = fmaf(s24.y, wR[24].y, a1);
            }
            buf2[t * HIDP + l] = a0 + a1;
        }
        {
            const float* row = sWic + (l < 18 ? (l + 32) : l) * HID;
            #pragma unroll
            for (int j = 0; j < 25; j++)
                wR[j] = make_float2(row[2 * j], row[2 * j + 1]);
        }
        #pragma unroll 1
        for (int t = w; t < TSTEPS; t += 8) {
            const float4* sp4 = (const float4*)&buf1[t * HIDP];
            float a0 = 0.f, a1 = 0.f;
            #pragma unroll
            for (int j = 0; j < 12; j++) {
                float4 s = sp4[j];
                a0 = fmaf(s.x, wR[2 * j].x, a0);
                a1 = fmaf(s.y, wR[2 * j].y, a1);
                a0 = fmaf(s.z, wR[2 * j + 1].x, a0);
                a1 = fmaf(s.w, wR[2 * j + 1].y, a1);
            }
            {
                float2 s24 = *(const float2*)&buf1[t * HIDP + 48];
                a0 = fmaf(s24.x, wR[24].x, a0);
                a1 = fmaf(s24.y, wR[24].y, a1);
            }
            if (l < 18) buf2[t * HIDP + 32 + l] = a0 + a1;
        }
    }
    __syncthreads();

    // ---- P4: IC membrane scans ----
    if (tid < HID) {
        float mem = 0.0f;
        #pragma unroll 4
        for (int t = 0; t < TSTEPS; t++) {
            float cur = buf2[t * HIDP + tid];
            mem = fmaf(beta, mem, cur);
            float spk = (mem > 1.0f) ? 1.0f : 0.0f;
            mem -= spk;
            buf2[t * HIDP + tid] = spk;
        }
    }
    __syncthreads();

    // ---- P5: AC GEMM, register weights from smem, float4 spike loads ----
    {
        float2 wR[25];
        {
            const float* row = sWac + (l < OUT ? l : 0) * HID;
            #pragma unroll
            for (int j = 0; j < 25; j++)
                wR[j] = make_float2(row[2 * j], row[2 * j + 1]);
        }
        #pragma unroll 1
        for (int t = w; t < TSTEPS; t += 8) {
            const float4* sp4 = (const float4*)&buf2[t * HIDP];
            float a0 = 0.f, a1 = 0.f;
            #pragma unroll
            for (int j = 0; j < 12; j++) {
                float4 s = sp4[j];
                a0 = fmaf(s.x, wR[2 * j].x, a0);
                a1 = fmaf(s.y, wR[2 * j].y, a1);
                a0 = fmaf(s.z, wR[2 * j + 1].x, a0);
                a1 = fmaf(s.w, wR[2 * j + 1].y, a1);
            }
            {
                float2 s24 = *(const float2*)&buf2[t * HIDP + 48];
                a0 = fmaf(s24.x, wR[24].x, a0);
                a1 = fmaf(s24.y, wR[24].y, a1);
            }
            if (l < OUT) bufAC[t * OUT + l] = a0 + a1;
        }
    }
    __syncthreads();

    // ---- P6: AC membrane scans (10 units) ----
    if (tid < OUT) {
        float mem = 0.0f;
        #pragma unroll 4
        for (int t = 0; t < TSTEPS; t++) {
            float cur = bufAC[t * OUT + tid];
            mem = fmaf(beta, mem, cur);
            float spk = (mem > 1.0f) ? 1.0f : 0.0f;
            mem -= spk;
            bufAC[t * OUT + tid] = spk;                    // in place
            bufAC[TSTEPS * OUT + t * OUT + tid] = mem;     // mem record
        }
    }
    __syncthreads();

    // ---- P7: coalesced output ----
    for (int i = tid; i < TSTEPS * OUT; i += 256) {
        out[b * (TSTEPS * OUT) + i]        = bufAC[i];
        out[half + b * (TSTEPS * OUT) + i] = bufAC[TSTEPS * OUT + i];
    }
}

// ---------------- launch ----------------
extern "C" void kernel_launch(void* const* d_in, const int* in_sizes, int n_in,
                              void* d_out, int out_size) {
    const float* audio = (const float*)d_in[0];
    const float* gt    = (const float*)d_in[1];
    const float* Wb    = (const float*)d_in[2];
    const float* Wic   = (const float*)d_in[3];
    const float* Wac   = (const float*)d_in[4];
    float* out = (float*)d_out;

    int B = in_sizes[0] / NSAMP;   // 256
    int half = out_size / 2;       // B*T*OUT

    static int smem_set = 0;
    if (!smem_set) {
        cudaFuncSetAttribute(scan_kernel, cudaFuncAttributeMaxDynamicSharedMemorySize,
                             SCAN_DYN_BYTES);
        smem_set = 1;
    }

    conv_pool_kernel<<<dim3(NGRPX + 1, B), 256>>>(audio, gt, Wb);
    scan_kernel<<<B, 256, SCAN_DYN_BYTES>>>(Wic, Wac, out, half);
}

// round 16
// speedup vs baseline: 1.0068x; 1.0068x over previous
#include <cuda_runtime.h>

// ---------------- problem constants ----------------
#define BATCH   256
#define NSAMP   16000
#define CCH     32
#define KTAP    64
#define NCHUNK  125          // 128-sample chunks covering 16000 samples
#define TSTEPS  124
#define HID     50
#define HIDP    52           // padded row stride (buf1/buf2)
#define SUFP    64           // SufW row stride (256B = 2 cache lines)
#define OUT     10
#define ANS     10

#define GROUP   8            // chunks per conv block (one per warp)
#define SEG     (GROUP*128)  // 1024 positions per block
#define SWIN    1088         // staged window length per shifted copy
#define SPITCH  1104         // padded copy pitch (floats)
#define NGRPX   16           // conv position groups

// scan kernel dynamic smem layout (floats)
#define BUF1_N  (TSTEPS * HIDP)          // 6448 : bushy cur -> spk (in place)
#define BUF2_N  (TSTEPS * HIDP)          // 6448 : IC cur -> spk (in place)
#define BUFAC_N (TSTEPS * OUT * 2)       // 2480 : AC cur->spk | mem
#define WIC_N   (HID * HID)              // 2500
#define WAC_N   (OUT * HID)              // 500
#define SCAN_DYN_FLOATS (BUF1_N + BUF2_N + BUFAC_N + WIC_N + WAC_N)
#define SCAN_DYN_BYTES  (SCAN_DYN_FLOATS * 4)

// ---------------- device scratch (no allocs allowed) ----------------
__device__ float  S_buf[BATCH * NCHUNK * CCH];                       // per-chunk relu sums
__device__ __align__(256) float SufW_g[CCH * (ANS + 1) * SUFP];      // 256B-row suffix sums

// ---------------- helpers ----------------
__device__ __forceinline__ unsigned s2u(const void* p) {
    return (unsigned)__cvta_generic_to_shared(p);
}
#define FFMA2(acc, a, b) \
    asm("fma.rn.f32x2 %0, %1, %2, %0;" : "+l"(acc) : "l"(a), "l"(b))
#define ADD2(acc, v) \
    asm("add.rn.f32x2 %0, %0, %1;" : "+l"(acc) : "l"(v))
#define LDSV2(lo, hi, addr) \
    asm("ld.shared.v2.b64 {%0, %1}, [%2];" : "=l"(lo), "=l"(hi) : "r"(addr))
#define LDG2U64(lo, hi, ptr) \
    asm("ld.global.nc.v2.u64 {%0, %1}, [%2];" : "=l"(lo), "=l"(hi) : "l"(ptr))

// ---------------- kernel B: fused gammatone conv + relu + chunk-sum ----------------
// grid (17, BATCH): blockIdx.x < 16 -> conv tile; blockIdx.x == 16, y == 0 -> prep.
__global__ void __launch_bounds__(256, 2) conv_pool_kernel(const float* __restrict__ audio,
                                                           const float* __restrict__ gt,
                                                           const float* __restrict__ Wb) {
    const int tid = threadIdx.x;

    if (blockIdx.x == NGRPX) {
        // ---- prep block: suffix sums of W_bushy into 256B rows ----
        if (blockIdx.y != 0) return;
        // zero pad columns h=50..63 of every row
        for (int i = tid; i < CCH * (ANS + 1) * 14; i += 256) {
            int r = i / 14, k = 50 + (i % 14);
            SufW_g[r * SUFP + k] = 0.0f;
        }
        // zero a=10 rows (h=0..49)
        for (int i = tid; i < CCH * HID; i += 256) {
            int c = i / HID, h = i % HID;
            SufW_g[(c * 11 + 10) * SUFP + h] = 0.0f;
        }
        // suffix sums
        for (int id = tid; id < HID * CCH; id += 256) {
            int h = id / CCH;
            int c = id % CCH;
            float v[ANS];
            #pragma unroll
            for (int a = 0; a < ANS; a++)
                v[a] = Wb[h * (CCH * ANS) + c * ANS + a];
            float s = 0.0f;
            #pragma unroll
            for (int a = ANS - 1; a >= 0; a--) {
                s += v[a];
                SufW_g[(c * 11 + a) * SUFP + h] = s;
            }
        }
        return;
    }

    const int grp = blockIdx.x;
    const int b   = blockIdx.y;
    __shared__ __align__(16) float s_copy[4][SPITCH];  // 4 shifted copies of audio window
    __shared__ float s_gt[KTAP * 33];                  // swizzled taps [k*33+c]

    const int P0  = grp * SEG;
    const float* abase = audio + b * NSAMP;

    #pragma unroll
    for (int s = 0; s < 4; s++) {
        for (int i = tid; i < SWIN; i += 256) {
            int n = P0 - 31 + i + s;
            s_copy[s][i] = (n >= 0 && n < NSAMP) ? abase[n] : 0.0f;
        }
    }
    for (int t = tid; t < CCH * KTAP; t += 256) {
        int c = t >> 6, k = t & 63;
        s_gt[k * 33 + c] = gt[t];
    }
    __syncthreads();

    const int c = tid & 31;   // channel = lane
    const int g = tid >> 5;   // warp id = local chunk

    unsigned long long kp[32];
    #pragma unroll
    for (int j = 0; j < 32; j++) {
        float t0 = s_gt[(2 * j) * 33 + c];
        float t1 = s_gt[(2 * j + 1) * 33 + c];
        asm("mov.b64 %0, {%1, %2};" : "=l"(kp[j]) : "f"(t0), "f"(t1));
    }

    const unsigned sbase = s2u(&s_copy[0][0]);
    float chunkacc = 0.0f;

    #pragma unroll 1
    for (int pass = 0; pass < 16; pass++) {
        const int h  = pass >> 2;        // 0..3 : which 32-position quarter
        const int c4 = pass & 3;         // copy index = position mod 4
        const int base = g * 128 + 32 * h;
        const unsigned addr = sbase + (unsigned)((c4 * SPITCH + base) * 4);

        unsigned long long accL[8], accH[8];
        #pragma unroll
        for (int j = 0; j < 8; j++) { accL[j] = 0ull; accH[j] = 0ull; }

        #pragma unroll
        for (int u = 0; u < 23; u++) {
            unsigned long long lo, hi;
            LDSV2(lo, hi, addr + 16u * (unsigned)u);
            #pragma unroll
            for (int j = 0; j < 8; j++) {
                const int m = u - j;
                if (m >= 0 && m < 16) {
                    FFMA2(accL[j], lo, kp[2 * m]);
                    FFMA2(accH[j], hi, kp[2 * m + 1]);
                }
            }
        }

        #pragma unroll
        for (int j = 0; j < 8; j++) {
            float l0, l1, h0, h1;
            asm("mov.b64 {%0, %1}, %2;" : "=f"(l0), "=f"(l1) : "l"(accL[j]));
            asm("mov.b64 {%0, %1}, %2;" : "=f"(h0), "=f"(h1) : "l"(accH[j]));
            float y = (l0 + l1) + (h0 + h1);
            chunkacc += fmaxf(y, 0.0f);
        }
    }

    const int j = grp * GROUP + g;
    if (j < NCHUNK)
        S_buf[(b * NCHUNK + j) * CCH + c] = chunkacc;
}

// ---------------- kernel C: phase-split LIF scan, smem-staged weights ----------------
// 256 threads per block, one block per batch element.
__global__ void __launch_bounds__(256, 2) scan_kernel(const float* __restrict__ Wic,
                                                      const float* __restrict__ Wac,
                                                      float* __restrict__ out, int half) {
    const int b = blockIdx.x;
    extern __shared__ __align__(16) float dyn[];
    float* buf1  = dyn;                  // [124][52] bushy cur -> spk
    float* buf2  = buf1 + BUF1_N;        // [124][52] IC cur -> spk
    float* bufAC = buf2 + BUF2_N;        // [124][10] AC spk | [124][10] AC mem
    float* sWic  = bufAC + BUFAC_N;      // [50*50] staged coalesced
    float* sWac  = sWic + WIC_N;         // [10*50]
    __shared__ unsigned short sOff[TSTEPS * CCH];

    const int tid = threadIdx.x;
    const int w   = tid >> 5;
    const int l   = tid & 31;
    const float beta = 0.95f;

    // ---- P0a: stage weights coalesced into smem ----
    for (int i = tid; i < WIC_N; i += 256) sWic[i] = __ldg(Wic + i);
    for (int i = tid; i < WAC_N; i += 256) sWac[i] = __ldg(Wac + i);

    // ---- P0b: per-(t,c) suffix offsets (row offsets in SUFP units) ----
    for (int x = tid; x < TSTEPS * CCH; x += 256) {
        int t = x >> 5, c = x & 31;
        float s0 = S_buf[(b * NCHUNK + t) * CCH + c];
        float s1 = S_buf[(b * NCHUNK + t + 1) * CCH + c];
        float env = (s0 + s1) * (1.0f / 256.0f);
        int cnt = 0;
        #pragma unroll
        for (int a = 0; a < ANS; a++) {
            float sc = 0.5f + (float)a * (1.0f / 9.0f);
            cnt += (env * sc - 0.5f) > 0.0f;
        }
        sOff[x] = (unsigned short)((c * 11 + (ANS - cnt)) * SUFP);
    }
    __syncthreads();

    // ---- P1: gather bushy input currents — warp = t-pair, lane = q (row-contiguous) ----
    // lanes 0-12 -> (t0, q=l), lanes 16-28 -> (t1, q=l-16); each LDG covers two
    // contiguous 256B rows -> 4 wavefronts instead of ~6 scattered.
    {
        const int tp = l >> 4;          // 0 or 1
        const int q  = l & 15;          // 0..15, active if < 13
        const bool act = (q < 13);
        #pragma unroll 1
        for (int t2 = w; t2 < TSTEPS / 2; t2 += 8) {
            const int t = 2 * t2 + tp;
            const unsigned short* off = &sOff[t * CCH];
            unsigned long long e01 = 0ull, e23 = 0ull, o01 = 0ull, o23 = 0ull;
            if (act) {
                #pragma unroll 8
                for (int c = 0; c < CCH; c += 2) {
                    unsigned long long a0, a1, b0, b1;
                    LDG2U64(a0, a1, SufW_g + off[c] + 4 * q);
                    LDG2U64(b0, b1, SufW_g + off[c + 1] + 4 * q);
                    ADD2(e01, a0); ADD2(e23, a1);
                    ADD2(o01, b0); ADD2(o23, b1);
                }
                unsigned long long r01, r23;
                asm("add.rn.f32x2 %0, %1, %2;" : "=l"(r01) : "l"(e01), "l"(o01));
                asm("add.rn.f32x2 %0, %1, %2;" : "=l"(r23) : "l"(e23), "l"(o23));
                unsigned saddr = s2u(&buf1[t * HIDP + 4 * q]);
                asm volatile("st.shared.v2.b64 [%0], {%1, %2};"
                             :: "r"(saddr), "l"(r01), "l"(r23));
            }
        }
    }
    __syncthreads();

    // ---- P2: bushy membrane scans (50 independent units) ----
    if (tid < HID) {
        float mem = 0.0f;
        #pragma unroll 4
        for (int t = 0; t < TSTEPS; t++) {
            float cur = buf1[t * HIDP + tid];
            mem = fmaf(beta, mem, cur);
            float spk = (mem > 1.0f) ? 1.0f : 0.0f;
            mem -= spk;
            buf1[t * HIDP + tid] = spk;    // in place: cur -> spk
        }
    }
    __syncthreads();

    // ---- P3: IC GEMM, register weights from smem, float4 spike loads ----
    {
        float2 wR[25];
        {
            const float* row = sWic + l * HID;
            #pragma unroll
            for (int j = 0; j < 25; j++)
                wR[j] = make_float2(row[2 * j], row[2 * j + 1]);
        }
        #pragma unroll 1
        for (int t = w; t < TSTEPS; t += 8) {
            const float4* sp4 = (const float4*)&buf1[t * HIDP];
            float a0 = 0.f, a1 = 0.f;
            #pragma unroll
            for (int j = 0; j < 12; j++) {
                float4 s = sp4[j];
                a0 = fmaf(s.x, wR[2 * j].x, a0);
                a1 = fmaf(s.y, wR[2 * j].y, a1);
                a0 = fmaf(s.z, wR[2 * j + 1].x, a0);
                a1 = fmaf(s.w, wR[2 * j + 1].y, a1);
            }
            {
                float2 s24 = *(const float2*)&buf1[t * HIDP + 48];
                a0 = fmaf(s24.x, wR[24].x, a0);
                a1 = fmaf(s24.y, wR[24].y, a1);
            }
            buf2[t * HIDP + l] = a0 + a1;
        }
        {
            const float* row = sWic + (l < 18 ? (l + 32) : l) * HID;
            #pragma unroll
            for (int j = 0; j < 25; j++)
                wR[j] = make_float2(row[2 * j], row[2 * j + 1]);
        }
        #pragma unroll 1
        for (int t = w; t < TSTEPS; t += 8) {
            const float4* sp4 = (const float4*)&buf1[t * HIDP];
            float a0 = 0.f, a1 = 0.f;
            #pragma unroll
            for (int j = 0; j < 12; j++) {
                float4 s = sp4[j];
                a0 = fmaf(s.x, wR[2 * j].x, a0);
                a1 = fmaf(s.y, wR[2 * j].y, a1);
                a0 = fmaf(s.z, wR[2 * j + 1].x, a0);
                a1 = fmaf(s.w, wR[2 * j + 1].y, a1);
            }
            {
                float2 s24 = *(const float2*)&buf1[t * HIDP + 48];
                a0 = fmaf(s24.x, wR[24].x, a0);
                a1 = fmaf(s24.y, wR[24].y, a1);
            }
            if (l < 18) buf2[t * HIDP + 32 + l] = a0 + a1;
        }
    }
    __syncthreads();

    // ---- P4: IC membrane scans ----
    if (tid < HID) {
        float mem = 0.0f;
        #pragma unroll 4
        for (int t = 0; t < TSTEPS; t++) {
            float cur = buf2[t * HIDP + tid];
            mem = fmaf(beta, mem, cur);
            float spk = (mem > 1.0f) ? 1.0f : 0.0f;
            mem -= spk;
            buf2[t * HIDP + tid] = spk;
        }
    }
    __syncthreads();

    // ---- P5: AC GEMM, register weights from smem, float4 spike loads ----
    {
        float2 wR[25];
        {
            const float* row = sWac + (l < OUT ? l : 0) * HID;
            #pragma unroll
            for (int j = 0; j < 25; j++)
                wR[j] = make_float2(row[2 * j], row[2 * j + 1]);
        }
        #pragma unroll 1
        for (int t = w; t < TSTEPS; t += 8) {
            const float4* sp4 = (const float4*)&buf2[t * HIDP];
            float a0 = 0.f, a1 = 0.f;
            #pragma unroll
            for (int j = 0; j < 12; j++) {
                float4 s = sp4[j];
                a0 = fmaf(s.x, wR[2 * j].x, a0);
                a1 = fmaf(s.y, wR[2 * j].y, a1);
                a0 = fmaf(s.z, wR[2 * j + 1].x, a0);
                a1 = fmaf(s.w, wR[2 * j + 1].y, a1);
            }
            {
                float2 s24 = *(const float2*)&buf2[t * HIDP + 48];
                a0 = fmaf(s24.x, wR[24].x, a0);
                a1 = fmaf(s24.y, wR[24].y, a1);
            }
            if (l < OUT) bufAC[t * OUT + l] = a0 + a1;
        }
    }
    __syncthreads();

    // ---- P6: AC membrane scans (10 units) ----
    if (tid < OUT) {
        float mem = 0.0f;
        #pragma unroll 4
        for (int t = 0; t < TSTEPS; t++) {
            float cur = bufAC[t * OUT + tid];
            mem = fmaf(beta, mem, cur);
            float spk = (mem > 1.0f) ? 1.0f : 0.0f;
            mem -= spk;
            bufAC[t * OUT + tid] = spk;                    // in place
            bufAC[TSTEPS * OUT + t * OUT + tid] = mem;     // mem record
        }
    }
    __syncthreads();

    // ---- P7: coalesced output ----
    for (int i = tid; i < TSTEPS * OUT; i += 256) {
        out[b * (TSTEPS * OUT) + i]        = bufAC[i];
        out[half + b * (TSTEPS * OUT) + i] = bufAC[TSTEPS * OUT + i];
    }
}

// ---------------- launch ----------------
extern "C" void kernel_launch(void* const* d_in, const int* in_sizes, int n_in,
                              void* d_out, int out_size) {
    const float* audio = (const float*)d_in[0];
    const float* gt    = (const float*)d_in[1];
    const float* Wb    = (const float*)d_in[2];
    const float* Wic   = (const float*)d_in[3];
    const float* Wac   = (const float*)d_in[4];
    float* out = (float*)d_out;

    int B = in_sizes[0] / NSAMP;   // 256
    int half = out_size / 2;       // B*T*OUT

    static int smem_set = 0;
    if (!smem_set) {
        cudaFuncSetAttribute(scan_kernel, cudaFuncAttributeMaxDynamicSharedMemorySize,
                             SCAN_DYN_BYTES);
        smem_set = 1;
    }

    conv_pool_kernel<<<dim3(NGRPX + 1, B), 256>>>(audio, gt, Wb);
    scan_kernel<<<B, 256, SCAN_DYN_BYTES>>>(Wic, Wac, out, half);
}